// round 16
// baseline (speedup 1.0000x reference)
#include <cuda_runtime.h>
#include <cuda_fp16.h>
#include <math.h>
#include <stdint.h>

// ---------------------------------------------------------------------------
// Problem constants: B=2, S=2048, C1=C2=1024, H=16, D=64, W_EXP=4
//   rows = B*S = 4096
// ---------------------------------------------------------------------------

// ---------------- scratch (static __device__ — allocation-free) ------------
__device__ __align__(16) __half g_xn [4096 * 1024];
__device__ __align__(16) __half g_yn [4096 * 1024];
__device__ __align__(16) __half g_wqp[1024 * 1024];   // [H*D][C]  (N x K)
__device__ __align__(16) __half g_wkp[1024 * 1024];
__device__ __align__(16) __half g_wvp[1024 * 1024];
__device__ __align__(16) __half g_w1t[1024 * 1024];   // [C1][H*D]
__device__ __align__(16) __half g_w2t[4096 * 1024];   // [4C1][C1]
__device__ __align__(16) __half g_w3t[1024 * 4096];   // [C1][4C1]
__device__ __align__(16) __half g_q  [4096 * 1024];   // pre-scaled by 0.125
__device__ __align__(16) __half g_k  [4096 * 1024];
__device__ __align__(16) __half g_v  [4096 * 1024];
__device__ __align__(16) __half g_o  [4096 * 1024];
__device__ __align__(16) __half g_h1 [4096 * 1024];
__device__ __align__(16) __half g_h2 [4096 * 4096];
__device__ __align__(16) float  g_xout[4096 * 1024];

// ---------------------------------------------------------------------------
// helpers
// ---------------------------------------------------------------------------
__device__ __forceinline__ void cp16(void* smem, const void* g) {
    uint32_t s = (uint32_t)__cvta_generic_to_shared(smem);
    asm volatile("cp.async.cg.shared.global [%0], [%1], 16;" :: "r"(s), "l"(g));
}
__device__ __forceinline__ void cp_commit() { asm volatile("cp.async.commit_group;"); }
__device__ __forceinline__ void cp_wait2()  { asm volatile("cp.async.wait_group 2;"); }
__device__ __forceinline__ void cp_wait1()  { asm volatile("cp.async.wait_group 1;"); }
__device__ __forceinline__ void cp_wait0()  { asm volatile("cp.async.wait_group 0;"); }

// m16n8k16 row.col f16 inputs, f32 accumulate
__device__ __forceinline__ void mma_f16(float* c, const uint32_t* a, const uint32_t* b) {
    asm volatile(
        "mma.sync.aligned.m16n8k16.row.col.f32.f16.f16.f32 "
        "{%0,%1,%2,%3}, {%4,%5,%6,%7}, {%8,%9}, {%0,%1,%2,%3};\n"
        : "+f"(c[0]), "+f"(c[1]), "+f"(c[2]), "+f"(c[3])
        : "r"(a[0]), "r"(a[1]), "r"(a[2]), "r"(a[3]), "r"(b[0]), "r"(b[1]));
}

// ldmatrix: 4x 8x8 b16 tiles. addr is a per-lane shared-space byte address.
__device__ __forceinline__ void ldsm4(uint32_t* r, uint32_t addr) {
    asm volatile("ldmatrix.sync.aligned.m8n8.x4.shared.b16 {%0,%1,%2,%3}, [%4];"
                 : "=r"(r[0]), "=r"(r[1]), "=r"(r[2]), "=r"(r[3]) : "r"(addr));
}
__device__ __forceinline__ void ldsm4t(uint32_t* r, uint32_t addr) {
    asm volatile("ldmatrix.sync.aligned.m8n8.x4.trans.shared.b16 {%0,%1,%2,%3}, [%4];"
                 : "=r"(r[0]), "=r"(r[1]), "=r"(r[2]), "=r"(r[3]) : "r"(addr));
}

__device__ __forceinline__ uint32_t f2h2(float lo, float hi) {
    __half2 h = __floats2half2_rn(lo, hi);
    return *(uint32_t*)&h;
}

// ---------------------------------------------------------------------------
// Dual LayerNorm: rows 0..4095 -> LN(x; ln1), rows 4096..8191 -> LN(y; ln2).
// ---------------------------------------------------------------------------
__global__ void ln2_kernel(const float* __restrict__ x, const float* __restrict__ y,
                           const float* __restrict__ w1, const float* __restrict__ b1,
                           const float* __restrict__ w2, const float* __restrict__ b2,
                           __half* __restrict__ ox, __half* __restrict__ oy)
{
    __shared__ float shs[8], shq[8];
    const int rid = blockIdx.x;
    const bool second = rid >= 4096;
    const int row = second ? rid - 4096 : rid;
    const float* xr = (second ? y : x) + (long long)row * 1024;
    const float* w  = second ? w2 : w1;
    const float* b  = second ? b2 : b1;
    __half* out     = (second ? oy : ox) + (long long)row * 1024;
    const int t = threadIdx.x;

    float4 f = *(const float4*)(xr + t * 4);
    float s = f.x + f.y + f.z + f.w;
    float q = f.x * f.x + f.y * f.y + f.z * f.z + f.w * f.w;
    #pragma unroll
    for (int o = 16; o; o >>= 1) {
        s += __shfl_xor_sync(0xFFFFFFFFu, s, o);
        q += __shfl_xor_sync(0xFFFFFFFFu, q, o);
    }
    const int wid = t >> 5, ln = t & 31;
    if (ln == 0) { shs[wid] = s; shq[wid] = q; }
    __syncthreads();
    if (wid == 0) {
        float a = (ln < 8) ? shs[ln] : 0.0f;
        float c = (ln < 8) ? shq[ln] : 0.0f;
        #pragma unroll
        for (int o = 4; o; o >>= 1) {
            a += __shfl_xor_sync(0xFFFFFFFFu, a, o);
            c += __shfl_xor_sync(0xFFFFFFFFu, c, o);
        }
        if (ln == 0) { shs[0] = a; shq[0] = c; }
    }
    __syncthreads();
    const float mu  = shs[0] * (1.0f / 1024.0f);
    const float var = shq[0] * (1.0f / 1024.0f) - mu * mu;
    const float rs  = rsqrtf(var + 1e-5f);

    float4 wv = *(const float4*)(w + t * 4);
    float4 bv = *(const float4*)(b + t * 4);
    uint2 o2;
    o2.x = f2h2((f.x - mu) * rs * wv.x + bv.x, (f.y - mu) * rs * wv.y + bv.y);
    o2.y = f2h2((f.z - mu) * rs * wv.z + bv.z, (f.w - mu) * rs * wv.w + bv.w);
    *(uint2*)(out + t * 4) = o2;
}

// single-input LayerNorm (for LN3)
__global__ void ln_kernel(const float* __restrict__ x,
                          const float* __restrict__ w,
                          const float* __restrict__ b,
                          __half* __restrict__ out)
{
    __shared__ float shs[8], shq[8];
    const int row = blockIdx.x;
    const float* xr = x + (long long)row * 1024;
    const int t = threadIdx.x;

    float4 f = *(const float4*)(xr + t * 4);
    float s = f.x + f.y + f.z + f.w;
    float q = f.x * f.x + f.y * f.y + f.z * f.z + f.w * f.w;
    #pragma unroll
    for (int o = 16; o; o >>= 1) {
        s += __shfl_xor_sync(0xFFFFFFFFu, s, o);
        q += __shfl_xor_sync(0xFFFFFFFFu, q, o);
    }
    const int wid = t >> 5, ln = t & 31;
    if (ln == 0) { shs[wid] = s; shq[wid] = q; }
    __syncthreads();
    if (wid == 0) {
        float a = (ln < 8) ? shs[ln] : 0.0f;
        float c = (ln < 8) ? shq[ln] : 0.0f;
        #pragma unroll
        for (int o = 4; o; o >>= 1) {
            a += __shfl_xor_sync(0xFFFFFFFFu, a, o);
            c += __shfl_xor_sync(0xFFFFFFFFu, c, o);
        }
        if (ln == 0) { shs[0] = a; shq[0] = c; }
    }
    __syncthreads();
    const float mu  = shs[0] * (1.0f / 1024.0f);
    const float var = shq[0] * (1.0f / 1024.0f) - mu * mu;
    const float rs  = rsqrtf(var + 1e-5f);

    float4 wv = *(const float4*)(w + t * 4);
    float4 bv = *(const float4*)(b + t * 4);
    uint2 o2;
    o2.x = f2h2((f.x - mu) * rs * wv.x + bv.x, (f.y - mu) * rs * wv.y + bv.y);
    o2.y = f2h2((f.z - mu) * rs * wv.z + bv.z, (f.w - mu) * rs * wv.w + bv.w);
    *(uint2*)(out + (long long)row * 1024 + t * 4) = o2;
}

// ---------------------------------------------------------------------------
// Merged transpose of li1/li2/li3 weights -> [N][K] fp16, one launch.
// block id < 1024: li1 (1024x1024); < 5120: li2 (K=1024 -> N=4096);
// else li3 (K=4096 -> N=1024). 32x32 tiles, block (32,8).
// ---------------------------------------------------------------------------
__global__ void transpose_lin(const float* __restrict__ li1_w,
                              const float* __restrict__ li2_w,
                              const float* __restrict__ li3_w)
{
    __shared__ float tile[32][33];
    const int id = blockIdx.x;
    const float* src; __half* dst; int srcLd, dstLd, n0, k0;
    if (id < 1024) {
        src = li1_w; dst = g_w1t; srcLd = 1024; dstLd = 1024;
        n0 = (id & 31) * 32;  k0 = (id >> 5) * 32;
    } else if (id < 5120) {
        const int l = id - 1024;
        src = li2_w; dst = g_w2t; srcLd = 4096; dstLd = 1024;
        n0 = (l & 127) * 32;  k0 = (l >> 7) * 32;
    } else {
        const int l = id - 5120;
        src = li3_w; dst = g_w3t; srcLd = 1024; dstLd = 4096;
        n0 = (l & 31) * 32;  k0 = (l >> 5) * 32;
    }
    const int tx = threadIdx.x, ty = threadIdx.y;
    #pragma unroll
    for (int j = 0; j < 32; j += 8)
        tile[ty + j][tx] = src[(long long)(k0 + ty + j) * srcLd + n0 + tx];
    __syncthreads();
    #pragma unroll
    for (int j = 0; j < 32; j += 8)
        dst[(long long)(n0 + ty + j) * dstLd + k0 + tx] = __float2half_rn(tile[tx][ty + j]);
}

// Fused per-head transpose of Wq/Wk/Wv [16][1024][64] -> [1024][1024] each.
__global__ void transpose_qkv(const float* __restrict__ Wq,
                              const float* __restrict__ Wk,
                              const float* __restrict__ Wv)
{
    __shared__ float tile[32][33];
    const int which = blockIdx.z >> 4;
    const int head  = blockIdx.z & 15;
    const float* s = (which == 0 ? Wq : which == 1 ? Wk : Wv) + head * 65536;
    __half*      d = (which == 0 ? g_wqp : which == 1 ? g_wkp : g_wvp) + head * 65536;
    const int n0 = blockIdx.x * 32, k0 = blockIdx.y * 32;
    const int tx = threadIdx.x, ty = threadIdx.y;
    #pragma unroll
    for (int j = 0; j < 32; j += 8)
        tile[ty + j][tx] = s[(long long)(k0 + ty + j) * 64 + n0 + tx];
    __syncthreads();
    #pragma unroll
    for (int j = 0; j < 32; j += 8)
        d[(long long)(n0 + ty + j) * 1024 + k0 + tx] = __float2half_rn(tile[tx][ty + j]);
}

// ---------------------------------------------------------------------------
// fp16 tensor-core GEMM body:  C[M][N] = epi(A[M][K] @ B[N][K]^T)
// CTA tile 128x128, BK=64 halves. 8 warps as 2M x 4N: warp tile 64x32.
// 2 CTAs/SM. cp.async 3-stage pipeline, ONE __syncthreads per iteration:
// load for stage kt+2 is issued right after the top barrier — its buffer
// ((kt+2)%3 == (kt-1)%3) was consumed in iteration kt-1, which every warp
// finished before passing this barrier.
// smem per stage: A,B tiles [128][72] halves (144B stride, conflict-free).
// EPI: 0 = half out, alpha*acc ; 1 = float out, acc+bias+res ;
//      2 = half out, gelu(acc+bias)
// ---------------------------------------------------------------------------
#define GH_TILE_BYTES  (128 * 72 * 2)              // 18432 per matrix
#define GH_STAGE_BYTES (2 * GH_TILE_BYTES)         // 36864
#define GH_SMEM_BYTES  (3 * GH_STAGE_BYTES)        // 110592 (3 stages)

template<int EPI>
__device__ __forceinline__ void gemm_body(
    int K,
    const __half* __restrict__ A, int lda,
    const __half* __restrict__ B, int ldb,
    void* __restrict__ Cout, int ldc,
    float alpha,
    const float* __restrict__ bias,
    const float* __restrict__ res, int ldr)
{
    extern __shared__ __half smem_g[];

    const int bm = blockIdx.y * 128;
    const int bn = blockIdx.x * 128;
    const int t    = threadIdx.x;
    const int warp = t >> 5;
    const int lane = t & 31;
    const int g  = lane >> 2;
    const int tg = lane & 3;
    const int wmBase = (warp >> 2) * 64;   // 2 warps in M
    const int wnBase = (warp & 3) * 32;    // 4 warps in N

    const int sub = lane >> 3, rr = lane & 7;
    const uint32_t ldoff72 = (uint32_t)(((rr + (sub & 1) * 8) * 72 + (sub >> 1) * 8) * 2);
    const uint32_t smb = (uint32_t)__cvta_generic_to_shared(smem_g);

    float acc[4][4][4];
    #pragma unroll
    for (int i = 0; i < 4; ++i)
        #pragma unroll
        for (int j = 0; j < 4; ++j)
            #pragma unroll
            for (int q = 0; q < 4; ++q) acc[i][j][q] = 0.0f;

    auto loadStage = [&](int kt, int buf) {
        __half* Ad = smem_g + buf * (GH_STAGE_BYTES / 2);
        __half* Bd = Ad + (GH_TILE_BYTES / 2);
        const __half* Ag = A + (long long)bm * lda + kt * 64;
        const __half* Bg = B + (long long)bn * ldb + kt * 64;
        #pragma unroll
        for (int i = 0; i < 4; ++i) {
            const int id = t + i * 256;          // 1024 chunks of 16B
            const int r = id >> 3, c = id & 7;
            cp16(&Ad[r * 72 + c * 8], Ag + (long long)r * lda + c * 8);
        }
        #pragma unroll
        for (int i = 0; i < 4; ++i) {
            const int id = t + i * 256;
            const int r = id >> 3, c = id & 7;
            cp16(&Bd[r * 72 + c * 8], Bg + (long long)r * ldb + c * 8);
        }
        cp_commit();
    };

    const int nk = K >> 6;
    loadStage(0, 0);
    if (nk > 1) loadStage(1, 1);

    for (int kt = 0; kt < nk; ++kt) {
        const int buf = kt % 3;
        if (kt + 1 < nk) cp_wait1(); else cp_wait0();
        __syncthreads();
        if (kt + 2 < nk) loadStage(kt + 2, (kt + 2) % 3);

        const uint32_t aBuf = smb + (uint32_t)(buf * GH_STAGE_BYTES);
        const uint32_t bBuf = aBuf + GH_TILE_BYTES;
        #pragma unroll
        for (int ks = 0; ks < 4; ++ks) {
            const int k0 = ks * 16;
            uint32_t a[4][4], b[4][2];
            #pragma unroll
            for (int mt = 0; mt < 4; ++mt)
                ldsm4(a[mt], aBuf + (uint32_t)(((wmBase + mt * 16) * 72 + k0) * 2) + ldoff72);
            #pragma unroll
            for (int p = 0; p < 2; ++p) {
                uint32_t rb[4];
                ldsm4(rb, bBuf + (uint32_t)(((wnBase + p * 16) * 72 + k0) * 2) + ldoff72);
                b[2 * p][0]     = rb[0]; b[2 * p][1]     = rb[2];
                b[2 * p + 1][0] = rb[1]; b[2 * p + 1][1] = rb[3];
            }
            #pragma unroll
            for (int mt = 0; mt < 4; ++mt)
                #pragma unroll
                for (int nt = 0; nt < 4; ++nt)
                    mma_f16(acc[mt][nt], a[mt], b[nt]);
        }
        // no trailing barrier: next iteration's top barrier protects reuse
    }

    // ---- epilogue ----
    #pragma unroll
    for (int mt = 0; mt < 4; ++mt) {
        #pragma unroll
        for (int nt = 0; nt < 4; ++nt) {
            const int r0 = bm + wmBase + mt * 16 + g;
            const int c0 = bn + wnBase + nt * 8 + 2 * tg;
            #pragma unroll
            for (int half = 0; half < 2; ++half) {
                const int r = r0 + half * 8;
                float v0 = acc[mt][nt][half * 2 + 0];
                float v1 = acc[mt][nt][half * 2 + 1];
                if (EPI == 0) {
                    v0 *= alpha; v1 *= alpha;
                    *(uint32_t*)((__half*)Cout + (long long)r * ldc + c0) = f2h2(v0, v1);
                } else if (EPI == 1) {
                    v0 += bias[c0]     + res[(long long)r * ldr + c0];
                    v1 += bias[c0 + 1] + res[(long long)r * ldr + c0 + 1];
                    float2 o; o.x = v0; o.y = v1;
                    *(float2*)((float*)Cout + (long long)r * ldc + c0) = o;
                } else {
                    const float z0 = v0 + bias[c0];
                    const float z1 = v1 + bias[c0 + 1];
                    v0 = 0.5f * z0 * (1.0f + erff(z0 * 0.70710678118654752440f));
                    v1 = 0.5f * z1 * (1.0f + erff(z1 * 0.70710678118654752440f));
                    *(uint32_t*)((__half*)Cout + (long long)r * ldc + c0) = f2h2(v0, v1);
                }
            }
        }
    }
}

template<int EPI>
__global__ __launch_bounds__(256, 2)
void gemm_h(int K,
            const __half* __restrict__ A, int lda,
            const __half* __restrict__ B, int ldb,
            void* __restrict__ Cout, int ldc,
            float alpha,
            const float* __restrict__ bias,
            const float* __restrict__ res, int ldr)
{
    gemm_body<EPI>(K, A, lda, B, ldb, Cout, ldc, alpha, bias, res, ldr);
}

// Merged Q/K/V projection: blockIdx.z selects {xn@wqp->q*0.125, yn@wkp->k, yn@wvp->v}
__global__ __launch_bounds__(256, 2)
void gemm_qkv()
{
    const int which = blockIdx.z;
    const __half* A = (which == 0) ? g_xn : g_yn;
    const __half* B = (which == 0) ? g_wqp : (which == 1) ? g_wkp : g_wvp;
    __half*       C = (which == 0) ? g_q   : (which == 1) ? g_k   : g_v;
    const float alpha = (which == 0) ? 0.125f : 1.0f;
    gemm_body<0>(1024, A, 1024, B, 1024, C, 1024, alpha, nullptr, nullptr, 0);
}

// ---------------------------------------------------------------------------
// Fused flash attention, fp16, post-softmax masking, 3-stage KV pipeline
// (one __syncthreads per iteration, same buffer-reuse argument as gemm_body).
// smem: sP [128][72] + sK[3][64][72] + sV[3][64][72] halves = 73728 B.
// ---------------------------------------------------------------------------
#define FA_SMEM_BYTES ((128*72 + 3*64*72 + 3*64*72) * 2)   // 73728

__global__ __launch_bounds__(256)
void flash_attn_kernel(const __half* __restrict__ Qg,
                       const __half* __restrict__ Kg,
                       const __half* __restrict__ Vg,
                       __half* __restrict__ Og)
{
    extern __shared__ __half sm_h[];
    __half* sP = sm_h;                           // [128][72]
    __half* sK = sm_h + 128 * 72;                // [3][64*72]
    __half* sV = sm_h + 128 * 72 + 3 * 64 * 72;  // [3][64*72]

    const int z = blockIdx.z;
    const long long zb = z >> 4, zh = z & 15;
    const long long base = zb * (2048LL * 1024) + zh * 64;
    const __half* Qp = Qg + base;
    const __half* Kp = Kg + base;
    const __half* Vp = Vg + base;

    const int bm = blockIdx.y * 128;
    const int t = threadIdx.x;
    const int w = t >> 5, lane = t & 31, g = lane >> 2, tg = lane & 3;

    const int sub = lane >> 3, rr = lane & 7;
    const uint32_t ldoff72 = (uint32_t)(((rr + (sub & 1) * 8) * 72 + (sub >> 1) * 8) * 2);
    const uint32_t sPb = (uint32_t)__cvta_generic_to_shared(sP);
    const uint32_t sKb = (uint32_t)__cvta_generic_to_shared(sK);
    const uint32_t sVb = (uint32_t)__cvta_generic_to_shared(sV);

    // ---- stage Q tile (128 x 64 halves) into sP ----
    {
        const __half* Qa = Qp + (long long)bm * 1024;
        #pragma unroll
        for (int i = 0; i < 4; ++i) {
            const int id = t + i * 256;
            const int m = id >> 3, c = id & 7;
            cp16(&sP[m * 72 + c * 8], Qa + (long long)m * 1024 + c * 8);
        }
        cp_commit();
    }

    auto loadKV = [&](int it, int buf) {
        const __half* Ka = Kp + (long long)(it * 64) * 1024;
        const __half* Va = Vp + (long long)(it * 64) * 1024;
        #pragma unroll
        for (int i = 0; i < 2; ++i) {
            const int id = t + i * 256;
            const int r = id >> 3, c = id & 7;
            cp16(&sK[buf * (64 * 72) + r * 72 + c * 8], Ka + (long long)r * 1024 + c * 8);
        }
        #pragma unroll
        for (int i = 0; i < 2; ++i) {
            const int id = t + i * 256;
            const int r = id >> 3, c = id & 7;
            cp16(&sV[buf * (64 * 72) + r * 72 + c * 8], Va + (long long)r * 1024 + c * 8);
        }
        cp_commit();
    };
    loadKV(0, 0);
    loadKV(1, 1);

    cp_wait2();                 // Q group done (KV0/KV1 may be pending)
    __syncthreads();

    // ---- Q fragments (already scaled by 0.125) via ldmatrix ----
    uint32_t aq[4][4];
    #pragma unroll
    for (int kk = 0; kk < 4; ++kk)
        ldsm4(aq[kk], sPb + (uint32_t)(((w * 16) * 72 + kk * 16) * 2) + ldoff72);

    float accO[8][4];
    #pragma unroll
    for (int i = 0; i < 8; ++i)
        #pragma unroll
        for (int j = 0; j < 4; ++j) accO[i][j] = 0.0f;
    float m0 = -1e30f, m1 = -1e30f, l0 = 0.0f, l1 = 0.0f;

    const int srow0 = bm + w * 16 + g;
    const int srow1 = srow0 + 8;

    for (int it = 0; it < 32; ++it) {
        const int buf = it % 3;
        if (it + 1 < 32) cp_wait1(); else cp_wait0();
        __syncthreads();
        if (it + 2 < 32) loadKV(it + 2, (it + 2) % 3);

        // ---- S = Q K^T ----
        float s[8][4];
        #pragma unroll
        for (int i = 0; i < 8; ++i) { s[i][0]=0; s[i][1]=0; s[i][2]=0; s[i][3]=0; }
        const uint32_t kBuf = sKb + (uint32_t)(buf * 64 * 72 * 2);
        #pragma unroll
        for (int kk = 0; kk < 4; ++kk) {
            const int k0 = kk * 16;
            uint32_t bfr[8][2];
            #pragma unroll
            for (int p = 0; p < 4; ++p) {
                uint32_t rb[4];
                ldsm4(rb, kBuf + (uint32_t)(((p * 16) * 72 + k0) * 2) + ldoff72);
                bfr[2 * p][0]     = rb[0]; bfr[2 * p][1]     = rb[2];
                bfr[2 * p + 1][0] = rb[1]; bfr[2 * p + 1][1] = rb[3];
            }
            #pragma unroll
            for (int nt = 0; nt < 8; ++nt)
                mma_f16(s[nt], aq[kk], bfr[nt]);
        }

        // ---- online softmax (l over ALL t; mask applies to P only) ----
        float tmax0 = s[0][0], tmax1 = s[0][2];
        #pragma unroll
        for (int nt = 0; nt < 8; ++nt) {
            tmax0 = fmaxf(tmax0, fmaxf(s[nt][0], s[nt][1]));
            tmax1 = fmaxf(tmax1, fmaxf(s[nt][2], s[nt][3]));
        }
        tmax0 = fmaxf(tmax0, __shfl_xor_sync(0xFFFFFFFFu, tmax0, 1));
        tmax0 = fmaxf(tmax0, __shfl_xor_sync(0xFFFFFFFFu, tmax0, 2));
        tmax1 = fmaxf(tmax1, __shfl_xor_sync(0xFFFFFFFFu, tmax1, 1));
        tmax1 = fmaxf(tmax1, __shfl_xor_sync(0xFFFFFFFFu, tmax1, 2));
        const float mn0 = fmaxf(m0, tmax0), mn1 = fmaxf(m1, tmax1);
        const float al0 = __expf(m0 - mn0), al1 = __expf(m1 - mn1);
        float ls0 = 0.0f, ls1 = 0.0f;
        #pragma unroll
        for (int nt = 0; nt < 8; ++nt) {
            s[nt][0] = __expf(s[nt][0] - mn0); ls0 += s[nt][0];
            s[nt][1] = __expf(s[nt][1] - mn0); ls0 += s[nt][1];
            s[nt][2] = __expf(s[nt][2] - mn1); ls1 += s[nt][2];
            s[nt][3] = __expf(s[nt][3] - mn1); ls1 += s[nt][3];
        }
        ls0 += __shfl_xor_sync(0xFFFFFFFFu, ls0, 1);
        ls0 += __shfl_xor_sync(0xFFFFFFFFu, ls0, 2);
        ls1 += __shfl_xor_sync(0xFFFFFFFFu, ls1, 1);
        ls1 += __shfl_xor_sync(0xFFFFFFFFu, ls1, 2);
        l0 = l0 * al0 + ls0;  l1 = l1 * al1 + ls1;
        m0 = mn0;  m1 = mn1;
        #pragma unroll
        for (int nt = 0; nt < 8; ++nt) {
            accO[nt][0] *= al0; accO[nt][1] *= al0;
            accO[nt][2] *= al1; accO[nt][3] *= al1;
        }

        const int tbase = it * 64;
        if (tbase + 63 > bm) {
            // ---- masked fp16 P -> sP (warp-private rows) ----
            #pragma unroll
            for (int nt = 0; nt < 8; ++nt) {
                const int tc = tbase + nt * 8 + 2 * tg;
                const float p0 = (tc     > srow0) ? s[nt][0] : 0.0f;
                const float p1 = (tc + 1 > srow0) ? s[nt][1] : 0.0f;
                const float p2 = (tc     > srow1) ? s[nt][2] : 0.0f;
                const float p3 = (tc + 1 > srow1) ? s[nt][3] : 0.0f;
                *(uint32_t*)&sP[(w * 16 + g)     * 72 + nt * 8 + 2 * tg] = f2h2(p0, p1);
                *(uint32_t*)&sP[(w * 16 + g + 8) * 72 + nt * 8 + 2 * tg] = f2h2(p2, p3);
            }
            __syncwarp();

            // ---- O += P V  (P via ldmatrix, V via ldmatrix.trans) ----
            const uint32_t vBuf = sVb + (uint32_t)(buf * 64 * 72 * 2);
            #pragma unroll
            for (int kk = 0; kk < 4; ++kk) {
                const int k0 = kk * 16;
                uint32_t a[4];
                ldsm4(a, sPb + (uint32_t)(((w * 16) * 72 + k0) * 2) + ldoff72);
                #pragma unroll
                for (int p = 0; p < 4; ++p) {
                    uint32_t rb[4];
                    ldsm4t(rb, vBuf + (uint32_t)((k0 * 72 + p * 16) * 2) + ldoff72);
                    uint32_t blo[2] = { rb[0], rb[1] };
                    uint32_t bhi[2] = { rb[2], rb[3] };
                    mma_f16(accO[2 * p],     a, blo);
                    mma_f16(accO[2 * p + 1], a, bhi);
                }
            }
        }
        // no trailing barrier (3-stage reuse protected by next top barrier)
    }

    // ---- epilogue: O /= l, write fp16 concat-head layout ----
    const float inv0 = 1.0f / l0, inv1 = 1.0f / l1;
    __half* Ob = Og + zb * (2048LL * 1024) + zh * 64;
    #pragma unroll
    for (int nt = 0; nt < 8; ++nt) {
        const int c = nt * 8 + 2 * tg;
        *(uint32_t*)(Ob + (long long)srow0 * 1024 + c) =
            f2h2(accO[nt][0] * inv0, accO[nt][1] * inv0);
        *(uint32_t*)(Ob + (long long)srow1 * 1024 + c) =
            f2h2(accO[nt][2] * inv1, accO[nt][3] * inv1);
    }
}

// ---------------------------------------------------------------------------
// Launch sequence (graph-capturable: kernel launches only)
// ---------------------------------------------------------------------------
extern "C" void kernel_launch(void* const* d_in, const int* in_sizes, int n_in,
                              void* d_out, int out_size)
{
    const float* x     = (const float*)d_in[0];
    const float* y     = (const float*)d_in[1];
    const float* Wq    = (const float*)d_in[2];
    const float* Wk    = (const float*)d_in[3];
    const float* Wv    = (const float*)d_in[4];
    const float* li1_w = (const float*)d_in[5];
    const float* li1_b = (const float*)d_in[6];
    const float* ln1_w = (const float*)d_in[7];
    const float* ln1_b = (const float*)d_in[8];
    const float* ln2_w = (const float*)d_in[9];
    const float* ln2_b = (const float*)d_in[10];
    const float* ln3_w = (const float*)d_in[11];
    const float* ln3_b = (const float*)d_in[12];
    const float* li2_w = (const float*)d_in[13];
    const float* li2_b = (const float*)d_in[14];
    const float* li3_w = (const float*)d_in[15];
    const float* li3_b = (const float*)d_in[16];
    float* out = (float*)d_out;

    __half *xn, *yn, *w1t, *w2t, *w3t;
    __half *qh, *kh, *vh, *oh, *h1, *h2;
    float *xo;
    cudaGetSymbolAddress((void**)&xn,  g_xn);
    cudaGetSymbolAddress((void**)&yn,  g_yn);
    cudaGetSymbolAddress((void**)&w1t, g_w1t);
    cudaGetSymbolAddress((void**)&w2t, g_w2t);
    cudaGetSymbolAddress((void**)&w3t, g_w3t);
    cudaGetSymbolAddress((void**)&qh,  g_q);
    cudaGetSymbolAddress((void**)&kh,  g_k);
    cudaGetSymbolAddress((void**)&vh,  g_v);
    cudaGetSymbolAddress((void**)&oh,  g_o);
    cudaGetSymbolAddress((void**)&h1,  g_h1);
    cudaGetSymbolAddress((void**)&h2,  g_h2);
    cudaGetSymbolAddress((void**)&xo,  g_xout);

    static int attr_set = 0;
    if (!attr_set) {
        cudaFuncSetAttribute(flash_attn_kernel,
                             cudaFuncAttributeMaxDynamicSharedMemorySize, FA_SMEM_BYTES);
        cudaFuncSetAttribute(gemm_qkv,
                             cudaFuncAttributeMaxDynamicSharedMemorySize, GH_SMEM_BYTES);
        cudaFuncSetAttribute(gemm_h<1>,
                             cudaFuncAttributeMaxDynamicSharedMemorySize, GH_SMEM_BYTES);
        cudaFuncSetAttribute(gemm_h<2>,
                             cudaFuncAttributeMaxDynamicSharedMemorySize, GH_SMEM_BYTES);
        attr_set = 1;
    }

    const dim3 tb(32, 8);

    // 1) LayerNorms of x and y (fp16 outputs) — one launch
    ln2_kernel<<<8192, 256>>>(x, y, ln1_w, ln1_b, ln2_w, ln2_b, xn, yn);

    // 2) Transpose-pack weights to [N][K] fp16 (two launches total)
    transpose_qkv<<<dim3(2, 32, 48), tb>>>(Wq, Wk, Wv);
    transpose_lin<<<9216, tb>>>(li1_w, li2_w, li3_w);

    // 3) Q/K/V projections, one launch (z selects operands; Q scaled 0.125)
    gemm_qkv<<<dim3(1024 / 128, 4096 / 128, 3), 256, GH_SMEM_BYTES>>>();

    // 4) Fused attention (scores + softmax + post-mask + PV)
    flash_attn_kernel<<<dim3(1, 16, 32), 256, FA_SMEM_BYTES>>>(qh, kh, vh, oh);

    // 5) x_out = x + O @ li1_w + li1_b  (fp32 out)
    dim3 gSq(1024 / 128, 4096 / 128);
    gemm_h<1><<<gSq, 256, GH_SMEM_BYTES>>>(1024, oh, 1024, w1t, 1024,
                                           xo, 1024, 1.0f, li1_b, x, 1024);

    // 6) h1 = LN(x_out) (fp16)
    ln_kernel<<<4096, 256>>>(xo, ln3_w, ln3_b, h1);

    // 7) h2 = gelu(h1 @ li2_w + li2_b)  (fp16)
    dim3 gUp(4096 / 128, 4096 / 128);
    gemm_h<2><<<gUp, 256, GH_SMEM_BYTES>>>(1024, h1, 1024, w2t, 1024,
                                           h2, 4096, 1.0f, li2_b, nullptr, 0);

    // 8) out = x_out + h2 @ li3_w + li3_b  (fp32 out)
    gemm_h<1><<<gSq, 256, GH_SMEM_BYTES>>>(4096, h2, 4096, w3t, 4096,
                                           out, 1024, 1.0f, li3_b, xo, 1024);
}

// round 17
// speedup vs baseline: 1.0116x; 1.0116x over previous
#include <cuda_runtime.h>
#include <cuda_fp16.h>
#include <math.h>
#include <stdint.h>

// ---------------------------------------------------------------------------
// Problem constants: B=2, S=2048, C1=C2=1024, H=16, D=64, W_EXP=4
//   rows = B*S = 4096
// ---------------------------------------------------------------------------

// ---------------- scratch (static __device__ — allocation-free) ------------
__device__ __align__(16) __half g_xn [4096 * 1024];
__device__ __align__(16) __half g_yn [4096 * 1024];
__device__ __align__(16) __half g_wqp[1024 * 1024];   // [H*D][C]  (N x K)
__device__ __align__(16) __half g_wkp[1024 * 1024];
__device__ __align__(16) __half g_wvp[1024 * 1024];
__device__ __align__(16) __half g_w1t[1024 * 1024];   // [C1][H*D]
__device__ __align__(16) __half g_w2t[4096 * 1024];   // [4C1][C1]
__device__ __align__(16) __half g_w3t[1024 * 4096];   // [C1][4C1]
__device__ __align__(16) __half g_q  [4096 * 1024];   // pre-scaled by 0.125
__device__ __align__(16) __half g_k  [4096 * 1024];
__device__ __align__(16) __half g_v  [4096 * 1024];
__device__ __align__(16) __half g_o  [4096 * 1024];
__device__ __align__(16) __half g_h1 [4096 * 1024];
__device__ __align__(16) __half g_h2 [4096 * 4096];
__device__ __align__(16) float  g_xout[4096 * 1024];

// ---------------------------------------------------------------------------
// helpers
// ---------------------------------------------------------------------------
__device__ __forceinline__ void cp16(void* smem, const void* g) {
    uint32_t s = (uint32_t)__cvta_generic_to_shared(smem);
    asm volatile("cp.async.cg.shared.global [%0], [%1], 16;" :: "r"(s), "l"(g));
}
__device__ __forceinline__ void cp_commit() { asm volatile("cp.async.commit_group;"); }
__device__ __forceinline__ void cp_wait2()  { asm volatile("cp.async.wait_group 2;"); }
__device__ __forceinline__ void cp_wait1()  { asm volatile("cp.async.wait_group 1;"); }
__device__ __forceinline__ void cp_wait0()  { asm volatile("cp.async.wait_group 0;"); }

// m16n8k16 row.col f16 inputs, f32 accumulate
__device__ __forceinline__ void mma_f16(float* c, const uint32_t* a, const uint32_t* b) {
    asm volatile(
        "mma.sync.aligned.m16n8k16.row.col.f32.f16.f16.f32 "
        "{%0,%1,%2,%3}, {%4,%5,%6,%7}, {%8,%9}, {%0,%1,%2,%3};\n"
        : "+f"(c[0]), "+f"(c[1]), "+f"(c[2]), "+f"(c[3])
        : "r"(a[0]), "r"(a[1]), "r"(a[2]), "r"(a[3]), "r"(b[0]), "r"(b[1]));
}

// ldmatrix: 4x 8x8 b16 tiles. addr is a per-lane shared-space byte address.
__device__ __forceinline__ void ldsm4(uint32_t* r, uint32_t addr) {
    asm volatile("ldmatrix.sync.aligned.m8n8.x4.shared.b16 {%0,%1,%2,%3}, [%4];"
                 : "=r"(r[0]), "=r"(r[1]), "=r"(r[2]), "=r"(r[3]) : "r"(addr));
}
__device__ __forceinline__ void ldsm4t(uint32_t* r, uint32_t addr) {
    asm volatile("ldmatrix.sync.aligned.m8n8.x4.trans.shared.b16 {%0,%1,%2,%3}, [%4];"
                 : "=r"(r[0]), "=r"(r[1]), "=r"(r[2]), "=r"(r[3]) : "r"(addr));
}

__device__ __forceinline__ uint32_t f2h2(float lo, float hi) {
    __half2 h = __floats2half2_rn(lo, hi);
    return *(uint32_t*)&h;
}

// ---------------------------------------------------------------------------
// Dual LayerNorm: rows 0..4095 -> LN(x; ln1), rows 4096..8191 -> LN(y; ln2).
// ---------------------------------------------------------------------------
__global__ void ln2_kernel(const float* __restrict__ x, const float* __restrict__ y,
                           const float* __restrict__ w1, const float* __restrict__ b1,
                           const float* __restrict__ w2, const float* __restrict__ b2,
                           __half* __restrict__ ox, __half* __restrict__ oy)
{
    __shared__ float shs[8], shq[8];
    const int rid = blockIdx.x;
    const bool second = rid >= 4096;
    const int row = second ? rid - 4096 : rid;
    const float* xr = (second ? y : x) + (long long)row * 1024;
    const float* w  = second ? w2 : w1;
    const float* b  = second ? b2 : b1;
    __half* out     = (second ? oy : ox) + (long long)row * 1024;
    const int t = threadIdx.x;

    float4 f = *(const float4*)(xr + t * 4);
    float s = f.x + f.y + f.z + f.w;
    float q = f.x * f.x + f.y * f.y + f.z * f.z + f.w * f.w;
    #pragma unroll
    for (int o = 16; o; o >>= 1) {
        s += __shfl_xor_sync(0xFFFFFFFFu, s, o);
        q += __shfl_xor_sync(0xFFFFFFFFu, q, o);
    }
    const int wid = t >> 5, ln = t & 31;
    if (ln == 0) { shs[wid] = s; shq[wid] = q; }
    __syncthreads();
    if (wid == 0) {
        float a = (ln < 8) ? shs[ln] : 0.0f;
        float c = (ln < 8) ? shq[ln] : 0.0f;
        #pragma unroll
        for (int o = 4; o; o >>= 1) {
            a += __shfl_xor_sync(0xFFFFFFFFu, a, o);
            c += __shfl_xor_sync(0xFFFFFFFFu, c, o);
        }
        if (ln == 0) { shs[0] = a; shq[0] = c; }
    }
    __syncthreads();
    const float mu  = shs[0] * (1.0f / 1024.0f);
    const float var = shq[0] * (1.0f / 1024.0f) - mu * mu;
    const float rs  = rsqrtf(var + 1e-5f);

    float4 wv = *(const float4*)(w + t * 4);
    float4 bv = *(const float4*)(b + t * 4);
    uint2 o2;
    o2.x = f2h2((f.x - mu) * rs * wv.x + bv.x, (f.y - mu) * rs * wv.y + bv.y);
    o2.y = f2h2((f.z - mu) * rs * wv.z + bv.z, (f.w - mu) * rs * wv.w + bv.w);
    *(uint2*)(out + t * 4) = o2;
}

// single-input LayerNorm (for LN3)
__global__ void ln_kernel(const float* __restrict__ x,
                          const float* __restrict__ w,
                          const float* __restrict__ b,
                          __half* __restrict__ out)
{
    __shared__ float shs[8], shq[8];
    const int row = blockIdx.x;
    const float* xr = x + (long long)row * 1024;
    const int t = threadIdx.x;

    float4 f = *(const float4*)(xr + t * 4);
    float s = f.x + f.y + f.z + f.w;
    float q = f.x * f.x + f.y * f.y + f.z * f.z + f.w * f.w;
    #pragma unroll
    for (int o = 16; o; o >>= 1) {
        s += __shfl_xor_sync(0xFFFFFFFFu, s, o);
        q += __shfl_xor_sync(0xFFFFFFFFu, q, o);
    }
    const int wid = t >> 5, ln = t & 31;
    if (ln == 0) { shs[wid] = s; shq[wid] = q; }
    __syncthreads();
    if (wid == 0) {
        float a = (ln < 8) ? shs[ln] : 0.0f;
        float c = (ln < 8) ? shq[ln] : 0.0f;
        #pragma unroll
        for (int o = 4; o; o >>= 1) {
            a += __shfl_xor_sync(0xFFFFFFFFu, a, o);
            c += __shfl_xor_sync(0xFFFFFFFFu, c, o);
        }
        if (ln == 0) { shs[0] = a; shq[0] = c; }
    }
    __syncthreads();
    const float mu  = shs[0] * (1.0f / 1024.0f);
    const float var = shq[0] * (1.0f / 1024.0f) - mu * mu;
    const float rs  = rsqrtf(var + 1e-5f);

    float4 wv = *(const float4*)(w + t * 4);
    float4 bv = *(const float4*)(b + t * 4);
    uint2 o2;
    o2.x = f2h2((f.x - mu) * rs * wv.x + bv.x, (f.y - mu) * rs * wv.y + bv.y);
    o2.y = f2h2((f.z - mu) * rs * wv.z + bv.z, (f.w - mu) * rs * wv.w + bv.w);
    *(uint2*)(out + (long long)row * 1024 + t * 4) = o2;
}

// ---------------------------------------------------------------------------
// Merged transpose of li1/li2/li3 weights -> [N][K] fp16, one launch.
// ---------------------------------------------------------------------------
__global__ void transpose_lin(const float* __restrict__ li1_w,
                              const float* __restrict__ li2_w,
                              const float* __restrict__ li3_w)
{
    __shared__ float tile[32][33];
    const int id = blockIdx.x;
    const float* src; __half* dst; int srcLd, dstLd, n0, k0;
    if (id < 1024) {
        src = li1_w; dst = g_w1t; srcLd = 1024; dstLd = 1024;
        n0 = (id & 31) * 32;  k0 = (id >> 5) * 32;
    } else if (id < 5120) {
        const int l = id - 1024;
        src = li2_w; dst = g_w2t; srcLd = 4096; dstLd = 1024;
        n0 = (l & 127) * 32;  k0 = (l >> 7) * 32;
    } else {
        const int l = id - 5120;
        src = li3_w; dst = g_w3t; srcLd = 1024; dstLd = 4096;
        n0 = (l & 31) * 32;  k0 = (l >> 5) * 32;
    }
    const int tx = threadIdx.x, ty = threadIdx.y;
    #pragma unroll
    for (int j = 0; j < 32; j += 8)
        tile[ty + j][tx] = src[(long long)(k0 + ty + j) * srcLd + n0 + tx];
    __syncthreads();
    #pragma unroll
    for (int j = 0; j < 32; j += 8)
        dst[(long long)(n0 + ty + j) * dstLd + k0 + tx] = __float2half_rn(tile[tx][ty + j]);
}

// Fused per-head transpose of Wq/Wk/Wv [16][1024][64] -> [1024][1024] each.
__global__ void transpose_qkv(const float* __restrict__ Wq,
                              const float* __restrict__ Wk,
                              const float* __restrict__ Wv)
{
    __shared__ float tile[32][33];
    const int which = blockIdx.z >> 4;
    const int head  = blockIdx.z & 15;
    const float* s = (which == 0 ? Wq : which == 1 ? Wk : Wv) + head * 65536;
    __half*      d = (which == 0 ? g_wqp : which == 1 ? g_wkp : g_wvp) + head * 65536;
    const int n0 = blockIdx.x * 32, k0 = blockIdx.y * 32;
    const int tx = threadIdx.x, ty = threadIdx.y;
    #pragma unroll
    for (int j = 0; j < 32; j += 8)
        tile[ty + j][tx] = s[(long long)(k0 + ty + j) * 64 + n0 + tx];
    __syncthreads();
    #pragma unroll
    for (int j = 0; j < 32; j += 8)
        d[(long long)(n0 + ty + j) * 1024 + k0 + tx] = __float2half_rn(tile[tx][ty + j]);
}

// ---------------------------------------------------------------------------
// fp16 tensor-core GEMM body (R14 pipeline + A-fragment rotation):
//   C[M][N] = epi(A[M][K] @ B[N][K]^T)
// CTA tile 128x128, BK=64 halves, 8 warps as 2M x 4N (warp tile 64x32),
// 2 CTAs/SM, cp.async double-buffered.
// Inner ks-step: load B frags + A frag(mt=0); then per mt prefetch A(mt+1)
// BEFORE issuing mt's MMAs — the ldsm retires under the MMA shadow, and the
// A-frag register footprint halves (16 -> 8 regs). MMA order unchanged
// (bitwise-identical accumulation vs R12/R14).
// EPI: 0 = half out, alpha*acc ; 1 = float out, acc+bias+res ;
//      2 = half out, gelu(acc+bias)
// ---------------------------------------------------------------------------
#define GH_TILE_BYTES  (128 * 72 * 2)              // 18432 per matrix
#define GH_STAGE_BYTES (2 * GH_TILE_BYTES)         // 36864
#define GH_SMEM_BYTES  (2 * GH_STAGE_BYTES)        // 73728

template<int EPI>
__device__ __forceinline__ void gemm_body(
    int K,
    const __half* __restrict__ A, int lda,
    const __half* __restrict__ B, int ldb,
    void* __restrict__ Cout, int ldc,
    float alpha,
    const float* __restrict__ bias,
    const float* __restrict__ res, int ldr)
{
    extern __shared__ __half smem_g[];

    const int bm = blockIdx.y * 128;
    const int bn = blockIdx.x * 128;
    const int t    = threadIdx.x;
    const int warp = t >> 5;
    const int lane = t & 31;
    const int g  = lane >> 2;
    const int tg = lane & 3;
    const int wmBase = (warp >> 2) * 64;   // 2 warps in M
    const int wnBase = (warp & 3) * 32;    // 4 warps in N

    const int sub = lane >> 3, rr = lane & 7;
    const uint32_t ldoff72 = (uint32_t)(((rr + (sub & 1) * 8) * 72 + (sub >> 1) * 8) * 2);
    const uint32_t smb = (uint32_t)__cvta_generic_to_shared(smem_g);

    float acc[4][4][4];
    #pragma unroll
    for (int i = 0; i < 4; ++i)
        #pragma unroll
        for (int j = 0; j < 4; ++j)
            #pragma unroll
            for (int q = 0; q < 4; ++q) acc[i][j][q] = 0.0f;

    auto loadStage = [&](int kt, int buf) {
        __half* Ad = smem_g + buf * (GH_STAGE_BYTES / 2);
        __half* Bd = Ad + (GH_TILE_BYTES / 2);
        const __half* Ag = A + (long long)bm * lda + kt * 64;
        const __half* Bg = B + (long long)bn * ldb + kt * 64;
        #pragma unroll
        for (int i = 0; i < 4; ++i) {
            const int id = t + i * 256;          // 1024 chunks of 16B
            const int r = id >> 3, c = id & 7;
            cp16(&Ad[r * 72 + c * 8], Ag + (long long)r * lda + c * 8);
        }
        #pragma unroll
        for (int i = 0; i < 4; ++i) {
            const int id = t + i * 256;
            const int r = id >> 3, c = id & 7;
            cp16(&Bd[r * 72 + c * 8], Bg + (long long)r * ldb + c * 8);
        }
        cp_commit();
    };

    const int nk = K >> 6;
    loadStage(0, 0);
    if (nk > 1) loadStage(1, 1);

    for (int kt = 0; kt < nk; ++kt) {
        const int buf = kt & 1;
        if (kt + 1 < nk) cp_wait1(); else cp_wait0();
        __syncthreads();

        const uint32_t aBuf = smb + (uint32_t)(buf * GH_STAGE_BYTES);
        const uint32_t bBuf = aBuf + GH_TILE_BYTES;
        #pragma unroll
        for (int ks = 0; ks < 4; ++ks) {
            const int k0 = ks * 16;
            uint32_t b[4][2];
            #pragma unroll
            for (int p = 0; p < 2; ++p) {
                uint32_t rb[4];
                ldsm4(rb, bBuf + (uint32_t)(((wnBase + p * 16) * 72 + k0) * 2) + ldoff72);
                b[2 * p][0]     = rb[0]; b[2 * p][1]     = rb[2];
                b[2 * p + 1][0] = rb[1]; b[2 * p + 1][1] = rb[3];
            }
            // A-fragment rotation: prefetch a(mt+1) before mt's MMAs.
            uint32_t afr[2][4];
            ldsm4(afr[0], aBuf + (uint32_t)((wmBase * 72 + k0) * 2) + ldoff72);
            #pragma unroll
            for (int mt = 0; mt < 4; ++mt) {
                if (mt < 3)
                    ldsm4(afr[(mt + 1) & 1],
                          aBuf + (uint32_t)(((wmBase + (mt + 1) * 16) * 72 + k0) * 2) + ldoff72);
                #pragma unroll
                for (int nt = 0; nt < 4; ++nt)
                    mma_f16(acc[mt][nt], afr[mt & 1], b[nt]);
            }
        }
        __syncthreads();
        if (kt + 2 < nk) loadStage(kt + 2, buf);
    }

    // ---- epilogue ----
    #pragma unroll
    for (int mt = 0; mt < 4; ++mt) {
        #pragma unroll
        for (int nt = 0; nt < 4; ++nt) {
            const int r0 = bm + wmBase + mt * 16 + g;
            const int c0 = bn + wnBase + nt * 8 + 2 * tg;
            #pragma unroll
            for (int half = 0; half < 2; ++half) {
                const int r = r0 + half * 8;
                float v0 = acc[mt][nt][half * 2 + 0];
                float v1 = acc[mt][nt][half * 2 + 1];
                if (EPI == 0) {
                    v0 *= alpha; v1 *= alpha;
                    *(uint32_t*)((__half*)Cout + (long long)r * ldc + c0) = f2h2(v0, v1);
                } else if (EPI == 1) {
                    v0 += bias[c0]     + res[(long long)r * ldr + c0];
                    v1 += bias[c0 + 1] + res[(long long)r * ldr + c0 + 1];
                    float2 o; o.x = v0; o.y = v1;
                    *(float2*)((float*)Cout + (long long)r * ldc + c0) = o;
                } else {
                    const float z0 = v0 + bias[c0];
                    const float z1 = v1 + bias[c0 + 1];
                    v0 = 0.5f * z0 * (1.0f + erff(z0 * 0.70710678118654752440f));
                    v1 = 0.5f * z1 * (1.0f + erff(z1 * 0.70710678118654752440f));
                    *(uint32_t*)((__half*)Cout + (long long)r * ldc + c0) = f2h2(v0, v1);
                }
            }
        }
    }
}

template<int EPI>
__global__ __launch_bounds__(256, 2)
void gemm_h(int K,
            const __half* __restrict__ A, int lda,
            const __half* __restrict__ B, int ldb,
            void* __restrict__ Cout, int ldc,
            float alpha,
            const float* __restrict__ bias,
            const float* __restrict__ res, int ldr)
{
    gemm_body<EPI>(K, A, lda, B, ldb, Cout, ldc, alpha, bias, res, ldr);
}

// Merged Q/K/V projection: blockIdx.z selects {xn@wqp->q*0.125, yn@wkp->k, yn@wvp->v}
__global__ __launch_bounds__(256, 2)
void gemm_qkv()
{
    const int which = blockIdx.z;
    const __half* A = (which == 0) ? g_xn : g_yn;
    const __half* B = (which == 0) ? g_wqp : (which == 1) ? g_wkp : g_wvp;
    __half*       C = (which == 0) ? g_q   : (which == 1) ? g_k   : g_v;
    const float alpha = (which == 0) ? 0.125f : 1.0f;
    gemm_body<0>(1024, A, 1024, B, 1024, C, 1024, alpha, nullptr, nullptr, 0);
}

// ---------------------------------------------------------------------------
// Fused flash attention (R12/R14 version: 2-stage KV pipeline, PV skip).
// ---------------------------------------------------------------------------
#define FA_SMEM_BYTES ((128*72 + 2*64*72 + 2*64*72) * 2)   // 55296

__global__ __launch_bounds__(256)
void flash_attn_kernel(const __half* __restrict__ Qg,
                       const __half* __restrict__ Kg,
                       const __half* __restrict__ Vg,
                       __half* __restrict__ Og)
{
    extern __shared__ __half sm_h[];
    __half* sP = sm_h;                           // [128][72]
    __half* sK = sm_h + 128 * 72;                // [2][64*72]
    __half* sV = sm_h + 128 * 72 + 2 * 64 * 72;  // [2][64*72]

    const int z = blockIdx.z;
    const long long zb = z >> 4, zh = z & 15;
    const long long base = zb * (2048LL * 1024) + zh * 64;
    const __half* Qp = Qg + base;
    const __half* Kp = Kg + base;
    const __half* Vp = Vg + base;

    const int bm = blockIdx.y * 128;
    const int t = threadIdx.x;
    const int w = t >> 5, lane = t & 31, g = lane >> 2, tg = lane & 3;

    const int sub = lane >> 3, rr = lane & 7;
    const uint32_t ldoff72 = (uint32_t)(((rr + (sub & 1) * 8) * 72 + (sub >> 1) * 8) * 2);
    const uint32_t sPb = (uint32_t)__cvta_generic_to_shared(sP);
    const uint32_t sKb = (uint32_t)__cvta_generic_to_shared(sK);
    const uint32_t sVb = (uint32_t)__cvta_generic_to_shared(sV);

    {
        const __half* Qa = Qp + (long long)bm * 1024;
        #pragma unroll
        for (int i = 0; i < 4; ++i) {
            const int id = t + i * 256;
            const int m = id >> 3, c = id & 7;
            cp16(&sP[m * 72 + c * 8], Qa + (long long)m * 1024 + c * 8);
        }
        cp_commit();
    }

    auto loadKV = [&](int it, int buf) {
        const __half* Ka = Kp + (long long)(it * 64) * 1024;
        const __half* Va = Vp + (long long)(it * 64) * 1024;
        #pragma unroll
        for (int i = 0; i < 2; ++i) {
            const int id = t + i * 256;
            const int r = id >> 3, c = id & 7;
            cp16(&sK[buf * (64 * 72) + r * 72 + c * 8], Ka + (long long)r * 1024 + c * 8);
        }
        #pragma unroll
        for (int i = 0; i < 2; ++i) {
            const int id = t + i * 256;
            const int r = id >> 3, c = id & 7;
            cp16(&sV[buf * (64 * 72) + r * 72 + c * 8], Va + (long long)r * 1024 + c * 8);
        }
        cp_commit();
    };
    loadKV(0, 0);
    loadKV(1, 1);

    cp_wait2();
    __syncthreads();

    uint32_t aq[4][4];
    #pragma unroll
    for (int kk = 0; kk < 4; ++kk)
        ldsm4(aq[kk], sPb + (uint32_t)(((w * 16) * 72 + kk * 16) * 2) + ldoff72);

    float accO[8][4];
    #pragma unroll
    for (int i = 0; i < 8; ++i)
        #pragma unroll
        for (int j = 0; j < 4; ++j) accO[i][j] = 0.0f;
    float m0 = -1e30f, m1 = -1e30f, l0 = 0.0f, l1 = 0.0f;

    const int srow0 = bm + w * 16 + g;
    const int srow1 = srow0 + 8;

    for (int it = 0; it < 32; ++it) {
        const int buf = it & 1;
        if (it + 1 < 32) cp_wait1(); else cp_wait0();
        __syncthreads();

        float s[8][4];
        #pragma unroll
        for (int i = 0; i < 8; ++i) { s[i][0]=0; s[i][1]=0; s[i][2]=0; s[i][3]=0; }
        const uint32_t kBuf = sKb + (uint32_t)(buf * 64 * 72 * 2);
        #pragma unroll
        for (int kk = 0; kk < 4; ++kk) {
            const int k0 = kk * 16;
            uint32_t bfr[8][2];
            #pragma unroll
            for (int p = 0; p < 4; ++p) {
                uint32_t rb[4];
                ldsm4(rb, kBuf + (uint32_t)(((p * 16) * 72 + k0) * 2) + ldoff72);
                bfr[2 * p][0]     = rb[0]; bfr[2 * p][1]     = rb[2];
                bfr[2 * p + 1][0] = rb[1]; bfr[2 * p + 1][1] = rb[3];
            }
            #pragma unroll
            for (int nt = 0; nt < 8; ++nt)
                mma_f16(s[nt], aq[kk], bfr[nt]);
        }

        float tmax0 = s[0][0], tmax1 = s[0][2];
        #pragma unroll
        for (int nt = 0; nt < 8; ++nt) {
            tmax0 = fmaxf(tmax0, fmaxf(s[nt][0], s[nt][1]));
            tmax1 = fmaxf(tmax1, fmaxf(s[nt][2], s[nt][3]));
        }
        tmax0 = fmaxf(tmax0, __shfl_xor_sync(0xFFFFFFFFu, tmax0, 1));
        tmax0 = fmaxf(tmax0, __shfl_xor_sync(0xFFFFFFFFu, tmax0, 2));
        tmax1 = fmaxf(tmax1, __shfl_xor_sync(0xFFFFFFFFu, tmax1, 1));
        tmax1 = fmaxf(tmax1, __shfl_xor_sync(0xFFFFFFFFu, tmax1, 2));
        const float mn0 = fmaxf(m0, tmax0), mn1 = fmaxf(m1, tmax1);
        const float al0 = __expf(m0 - mn0), al1 = __expf(m1 - mn1);
        float ls0 = 0.0f, ls1 = 0.0f;
        #pragma unroll
        for (int nt = 0; nt < 8; ++nt) {
            s[nt][0] = __expf(s[nt][0] - mn0); ls0 += s[nt][0];
            s[nt][1] = __expf(s[nt][1] - mn0); ls0 += s[nt][1];
            s[nt][2] = __expf(s[nt][2] - mn1); ls1 += s[nt][2];
            s[nt][3] = __expf(s[nt][3] - mn1); ls1 += s[nt][3];
        }
        ls0 += __shfl_xor_sync(0xFFFFFFFFu, ls0, 1);
        ls0 += __shfl_xor_sync(0xFFFFFFFFu, ls0, 2);
        ls1 += __shfl_xor_sync(0xFFFFFFFFu, ls1, 1);
        ls1 += __shfl_xor_sync(0xFFFFFFFFu, ls1, 2);
        l0 = l0 * al0 + ls0;  l1 = l1 * al1 + ls1;
        m0 = mn0;  m1 = mn1;
        #pragma unroll
        for (int nt = 0; nt < 8; ++nt) {
            accO[nt][0] *= al0; accO[nt][1] *= al0;
            accO[nt][2] *= al1; accO[nt][3] *= al1;
        }

        const int tbase = it * 64;
        if (tbase + 63 > bm) {
            #pragma unroll
            for (int nt = 0; nt < 8; ++nt) {
                const int tc = tbase + nt * 8 + 2 * tg;
                const float p0 = (tc     > srow0) ? s[nt][0] : 0.0f;
                const float p1 = (tc + 1 > srow0) ? s[nt][1] : 0.0f;
                const float p2 = (tc     > srow1) ? s[nt][2] : 0.0f;
                const float p3 = (tc + 1 > srow1) ? s[nt][3] : 0.0f;
                *(uint32_t*)&sP[(w * 16 + g)     * 72 + nt * 8 + 2 * tg] = f2h2(p0, p1);
                *(uint32_t*)&sP[(w * 16 + g + 8) * 72 + nt * 8 + 2 * tg] = f2h2(p2, p3);
            }
            __syncwarp();

            const uint32_t vBuf = sVb + (uint32_t)(buf * 64 * 72 * 2);
            #pragma unroll
            for (int kk = 0; kk < 4; ++kk) {
                const int k0 = kk * 16;
                uint32_t a[4];
                ldsm4(a, sPb + (uint32_t)(((w * 16) * 72 + k0) * 2) + ldoff72);
                #pragma unroll
                for (int p = 0; p < 4; ++p) {
                    uint32_t rb[4];
                    ldsm4t(rb, vBuf + (uint32_t)((k0 * 72 + p * 16) * 2) + ldoff72);
                    uint32_t blo[2] = { rb[0], rb[1] };
                    uint32_t bhi[2] = { rb[2], rb[3] };
                    mma_f16(accO[2 * p],     a, blo);
                    mma_f16(accO[2 * p + 1], a, bhi);
                }
            }
        }
        __syncthreads();
        if (it + 2 < 32) loadKV(it + 2, buf);
    }

    const float inv0 = 1.0f / l0, inv1 = 1.0f / l1;
    __half* Ob = Og + zb * (2048LL * 1024) + zh * 64;
    #pragma unroll
    for (int nt = 0; nt < 8; ++nt) {
        const int c = nt * 8 + 2 * tg;
        *(uint32_t*)(Ob + (long long)srow0 * 1024 + c) =
            f2h2(accO[nt][0] * inv0, accO[nt][1] * inv0);
        *(uint32_t*)(Ob + (long long)srow1 * 1024 + c) =
            f2h2(accO[nt][2] * inv1, accO[nt][3] * inv1);
    }
}

// ---------------------------------------------------------------------------
// Launch sequence (graph-capturable: kernel launches only)
// ---------------------------------------------------------------------------
extern "C" void kernel_launch(void* const* d_in, const int* in_sizes, int n_in,
                              void* d_out, int out_size)
{
    const float* x     = (const float*)d_in[0];
    const float* y     = (const float*)d_in[1];
    const float* Wq    = (const float*)d_in[2];
    const float* Wk    = (const float*)d_in[3];
    const float* Wv    = (const float*)d_in[4];
    const float* li1_w = (const float*)d_in[5];
    const float* li1_b = (const float*)d_in[6];
    const float* ln1_w = (const float*)d_in[7];
    const float* ln1_b = (const float*)d_in[8];
    const float* ln2_w = (const float*)d_in[9];
    const float* ln2_b = (const float*)d_in[10];
    const float* ln3_w = (const float*)d_in[11];
    const float* ln3_b = (const float*)d_in[12];
    const float* li2_w = (const float*)d_in[13];
    const float* li2_b = (const float*)d_in[14];
    const float* li3_w = (const float*)d_in[15];
    const float* li3_b = (const float*)d_in[16];
    float* out = (float*)d_out;

    __half *xn, *yn, *w1t, *w2t, *w3t;
    __half *qh, *kh, *vh, *oh, *h1, *h2;
    float *xo;
    cudaGetSymbolAddress((void**)&xn,  g_xn);
    cudaGetSymbolAddress((void**)&yn,  g_yn);
    cudaGetSymbolAddress((void**)&w1t, g_w1t);
    cudaGetSymbolAddress((void**)&w2t, g_w2t);
    cudaGetSymbolAddress((void**)&w3t, g_w3t);
    cudaGetSymbolAddress((void**)&qh,  g_q);
    cudaGetSymbolAddress((void**)&kh,  g_k);
    cudaGetSymbolAddress((void**)&vh,  g_v);
    cudaGetSymbolAddress((void**)&oh,  g_o);
    cudaGetSymbolAddress((void**)&h1,  g_h1);
    cudaGetSymbolAddress((void**)&h2,  g_h2);
    cudaGetSymbolAddress((void**)&xo,  g_xout);

    static int attr_set = 0;
    if (!attr_set) {
        cudaFuncSetAttribute(flash_attn_kernel,
                             cudaFuncAttributeMaxDynamicSharedMemorySize, FA_SMEM_BYTES);
        cudaFuncSetAttribute(gemm_qkv,
                             cudaFuncAttributeMaxDynamicSharedMemorySize, GH_SMEM_BYTES);
        cudaFuncSetAttribute(gemm_h<1>,
                             cudaFuncAttributeMaxDynamicSharedMemorySize, GH_SMEM_BYTES);
        cudaFuncSetAttribute(gemm_h<2>,
                             cudaFuncAttributeMaxDynamicSharedMemorySize, GH_SMEM_BYTES);
        attr_set = 1;
    }

    const dim3 tb(32, 8);

    // 1) LayerNorms of x and y (fp16 outputs) — one launch
    ln2_kernel<<<8192, 256>>>(x, y, ln1_w, ln1_b, ln2_w, ln2_b, xn, yn);

    // 2) Transpose-pack weights to [N][K] fp16 (two launches total)
    transpose_qkv<<<dim3(2, 32, 48), tb>>>(Wq, Wk, Wv);
    transpose_lin<<<9216, tb>>>(li1_w, li2_w, li3_w);

    // 3) Q/K/V projections, one launch (z selects operands; Q scaled 0.125)
    gemm_qkv<<<dim3(1024 / 128, 4096 / 128, 3), 256, GH_SMEM_BYTES>>>();

    // 4) Fused attention (scores + softmax + post-mask + PV)
    flash_attn_kernel<<<dim3(1, 16, 32), 256, FA_SMEM_BYTES>>>(qh, kh, vh, oh);

    // 5) x_out = x + O @ li1_w + li1_b  (fp32 out)
    dim3 gSq(1024 / 128, 4096 / 128);
    gemm_h<1><<<gSq, 256, GH_SMEM_BYTES>>>(1024, oh, 1024, w1t, 1024,
                                           xo, 1024, 1.0f, li1_b, x, 1024);

    // 6) h1 = LN(x_out) (fp16)
    ln_kernel<<<4096, 256>>>(xo, ln3_w, ln3_b, h1);

    // 7) h2 = gelu(h1 @ li2_w + li2_b)  (fp16)
    dim3 gUp(4096 / 128, 4096 / 128);
    gemm_h<2><<<gUp, 256, GH_SMEM_BYTES>>>(1024, h1, 1024, w2t, 1024,
                                           h2, 4096, 1.0f, li2_b, nullptr, 0);

    // 8) out = x_out + h2 @ li3_w + li3_b  (fp32 out)
    gemm_h<1><<<gSq, 256, GH_SMEM_BYTES>>>(4096, h2, 4096, w3t, 4096,
                                           out, 1024, 1.0f, li3_b, xo, 1024);
}